// round 2
// baseline (speedup 1.0000x reference)
#include <cuda_runtime.h>
#include <cstddef>

// ---------------------------------------------------------------------------
// MultiScaleAttention: out = softmax((x@Wq) (ctx@Wk)^T * d^-0.5) (ctx@Wv) @ Wo + bo
// Shapes: x[2,1024,4,512] -> rows 8192; context[2,2048,512] -> rows 4096;
// Wq[512,512], Wkv[512,1024], Wo[512,512], bo[512]. H=8, D=64, M=2048.
// ---------------------------------------------------------------------------

#define BATCH   2
#define NROWS   8192          // B * N * S
#define CROWS   4096          // B * M
#define QDIM    512
#define INNER   512
#define KVDIM   1024
#define HEADS   8
#define DHEAD   64
#define MCTX    2048

// Scratch (static device allocations are the sanctioned workaround)
__device__ float g_q [NROWS * INNER];    // 16 MB
__device__ float g_kv[CROWS * KVDIM];    // 16 MB
__device__ float g_ao[NROWS * INNER];    // 16 MB

// ---------------------------------------------------------------------------
// Generic fp32 tiled GEMM: C[M,N] = A[M,K] @ B[K,N] (+ bias[n])
// BM=BN=64, BK=16, 256 threads, 4x4 microtile, float4 smem fragments.
// Padding stride 68 floats: column offsets that are multiples of 4 stay
// 16B-aligned for LDS.128 (stride 65 trapped with misaligned address).
// ---------------------------------------------------------------------------
template <bool HAS_BIAS>
__global__ __launch_bounds__(256)
void gemm64(const float* __restrict__ A, const float* __restrict__ B,
            const float* __restrict__ bias, float* __restrict__ C,
            int M, int N, int K)
{
    __shared__ float As[16][68];   // [kk][row]  (transposed on load)
    __shared__ float Bs[16][64];   // [kk][col]

    const int bm  = blockIdx.y * 64;
    const int bn  = blockIdx.x * 64;
    const int tid = threadIdx.x;
    const int tx  = tid & 15;      // 16 col-groups
    const int ty  = tid >> 4;      // 16 row-groups

    float acc[4][4] = {};

    for (int k0 = 0; k0 < K; k0 += 16) {
        #pragma unroll
        for (int i = 0; i < 4; i++) {
            int idx = tid + i * 256;          // 0..1023 over 64x16 A tile
            int kk = idx & 15, row = idx >> 4;
            As[kk][row] = A[(size_t)(bm + row) * K + k0 + kk];
        }
        #pragma unroll
        for (int i = 0; i < 4; i++) {
            int idx = tid + i * 256;          // 0..1023 over 16x64 B tile
            int c = idx & 63, kk = idx >> 6;
            Bs[kk][c] = B[(size_t)(k0 + kk) * N + bn + c];
        }
        __syncthreads();

        #pragma unroll
        for (int kk = 0; kk < 16; kk++) {
            float4 a4 = *(const float4*)&As[kk][ty * 4];
            float4 b4 = *(const float4*)&Bs[kk][tx * 4];
            float av[4] = {a4.x, a4.y, a4.z, a4.w};
            float bv[4] = {b4.x, b4.y, b4.z, b4.w};
            #pragma unroll
            for (int i = 0; i < 4; i++)
                #pragma unroll
                for (int j = 0; j < 4; j++)
                    acc[i][j] += av[i] * bv[j];
        }
        __syncthreads();
    }

    #pragma unroll
    for (int i = 0; i < 4; i++) {
        #pragma unroll
        for (int j = 0; j < 4; j++) {
            float v = acc[i][j];
            if (HAS_BIAS) v += bias[bn + tx * 4 + j];
            C[(size_t)(bm + ty * 4 + i) * N + bn + tx * 4 + j] = v;
        }
    }
}

// ---------------------------------------------------------------------------
// Flash attention, fp32. One block per (batch, head, 64-query tile).
// Q/K stored d-major in smem so QK^T fragments are float4 loads.
// All tile strides are 68 floats (16B-aligned float4 columns).
// ---------------------------------------------------------------------------
#define SM_FLOATS (64*68*4 + 192)

__global__ __launch_bounds__(256)
void attn64(const float* __restrict__ q, const float* __restrict__ kv,
            float* __restrict__ o)
{
    extern __shared__ float sm[];
    float* Qs    = sm;                 // [d][row]   64x68
    float* Ks    = Qs + 64 * 68;       // [d][key]   64x68
    float* Vs    = Ks + 64 * 68;       // [key][d]   64x68
    float* Ps    = Vs + 64 * 68;       // [row][key] 64x68
    float* row_m = Ps + 64 * 68;       // 64
    float* row_l = row_m + 64;         // 64
    float* row_c = row_l + 64;         // 64

    const int bx = blockIdx.x;
    const int qt = bx & 63;
    const int h  = (bx >> 6) & 7;
    const int b  = bx >> 9;

    const int tid = threadIdx.x;
    const int tx  = tid & 15;
    const int ty  = tid >> 4;
    const int r0  = ty * 4;
    const int c0  = tx * 4;

    const float* qbase = q  + (size_t)(b * 4096 + qt * 64) * INNER + h * DHEAD;
    const float* kbase = kv + (size_t)b * MCTX * KVDIM + h * DHEAD;
    const float* vbase = kbase + INNER;   // v half of kv

    // Load Q tile (pre-scaled by d^-0.5), transposed to d-major
    for (int i = tid; i < 4096; i += 256) {
        int r = i >> 6, d = i & 63;
        Qs[d * 68 + r] = qbase[(size_t)r * INNER + d] * 0.125f;
    }
    if (tid < 64) { row_m[tid] = -1e30f; row_l[tid] = 0.0f; }

    float acc[4][4] = {};

    for (int m0 = 0; m0 < MCTX; m0 += 64) {
        __syncthreads();   // previous PV reads of Ps/Vs done; Q load visible
        for (int i = tid; i < 4096; i += 256) {
            int m = i >> 6, d = i & 63;
            size_t roff = (size_t)(m0 + m) * KVDIM + d;
            Ks[d * 68 + m] = kbase[roff];
            Vs[m * 68 + d] = vbase[roff];
        }
        __syncthreads();

        // S = Q K^T (64x64x64)
        float s[4][4] = {};
        #pragma unroll 8
        for (int d = 0; d < 64; d++) {
            float4 qa = *(const float4*)&Qs[d * 68 + r0];
            float4 kb = *(const float4*)&Ks[d * 68 + c0];
            float av[4] = {qa.x, qa.y, qa.z, qa.w};
            float bv[4] = {kb.x, kb.y, kb.z, kb.w};
            #pragma unroll
            for (int i = 0; i < 4; i++)
                #pragma unroll
                for (int j = 0; j < 4; j++)
                    s[i][j] += av[i] * bv[j];
        }
        #pragma unroll
        for (int i = 0; i < 4; i++)
            *(float4*)&Ps[(r0 + i) * 68 + c0] =
                make_float4(s[i][0], s[i][1], s[i][2], s[i][3]);
        __syncthreads();

        // Online softmax, one thread per query row
        if (tid < 64) {
            float* prow = Ps + tid * 68;
            float mold = row_m[tid];
            float mnew = mold;
            #pragma unroll 8
            for (int j = 0; j < 64; j++) mnew = fmaxf(mnew, prow[j]);
            float corr = __expf(mold - mnew);
            float sum = 0.0f;
            #pragma unroll 8
            for (int j = 0; j < 64; j++) {
                float e = __expf(prow[j] - mnew);
                prow[j] = e;
                sum += e;
            }
            row_m[tid] = mnew;
            row_c[tid] = corr;
            row_l[tid] = row_l[tid] * corr + sum;
        }
        __syncthreads();

        // O = O*corr + P @ V
        float cr[4];
        #pragma unroll
        for (int i = 0; i < 4; i++) cr[i] = row_c[r0 + i];
        #pragma unroll
        for (int i = 0; i < 4; i++)
            #pragma unroll
            for (int j = 0; j < 4; j++)
                acc[i][j] *= cr[i];

        #pragma unroll 8
        for (int m = 0; m < 64; m++) {
            float4 vb = *(const float4*)&Vs[m * 68 + c0];
            float bv[4] = {vb.x, vb.y, vb.z, vb.w};
            float pv[4];
            #pragma unroll
            for (int i = 0; i < 4; i++) pv[i] = Ps[(r0 + i) * 68 + m];
            #pragma unroll
            for (int i = 0; i < 4; i++)
                #pragma unroll
                for (int j = 0; j < 4; j++)
                    acc[i][j] += pv[i] * bv[j];
        }
    }

    float* obase = o + (size_t)(b * 4096 + qt * 64) * INNER + h * DHEAD;
    #pragma unroll
    for (int i = 0; i < 4; i++) {
        float inv = 1.0f / row_l[r0 + i];
        #pragma unroll
        for (int j = 0; j < 4; j++)
            obase[(size_t)(r0 + i) * INNER + c0 + j] = acc[i][j] * inv;
    }
}

// ---------------------------------------------------------------------------
extern "C" void kernel_launch(void* const* d_in, const int* in_sizes, int n_in,
                              void* d_out, int out_size)
{
    const float* x   = (const float*)d_in[0];
    const float* ctx = (const float*)d_in[1];
    const float* Wq  = (const float*)d_in[2];
    const float* Wkv = (const float*)d_in[3];
    const float* Wo  = (const float*)d_in[4];
    const float* bo  = (const float*)d_in[5];
    float* out = (float*)d_out;

    float *qp = nullptr, *kvp = nullptr, *aop = nullptr;
    cudaGetSymbolAddress((void**)&qp,  g_q);
    cudaGetSymbolAddress((void**)&kvp, g_kv);
    cudaGetSymbolAddress((void**)&aop, g_ao);

    // Q projection: [8192,512] = x @ Wq
    gemm64<false><<<dim3(INNER / 64, NROWS / 64), 256>>>(
        x, Wq, nullptr, qp, NROWS, INNER, QDIM);

    // KV projection: [4096,1024] = ctx @ Wkv
    gemm64<false><<<dim3(KVDIM / 64, CROWS / 64), 256>>>(
        ctx, Wkv, nullptr, kvp, CROWS, KVDIM, QDIM);

    // Attention: 2 batches x 8 heads x 64 query tiles
    const size_t smem_bytes = SM_FLOATS * sizeof(float);   // ~69.6 KB
    cudaFuncSetAttribute(attn64, cudaFuncAttributeMaxDynamicSharedMemorySize,
                         (int)smem_bytes);
    attn64<<<BATCH * HEADS * 64, 256, smem_bytes>>>(qp, kvp, aop);

    // Output projection + bias
    gemm64<true><<<dim3(INNER / 64, NROWS / 64), 256>>>(
        aop, Wo, bo, out, NROWS, INNER, INNER);
}

// round 3
// speedup vs baseline: 1.0002x; 1.0002x over previous
#include <cuda_runtime.h>
#include <cstddef>

// ---------------------------------------------------------------------------
// MultiScaleAttention: out = softmax((x@Wq) (ctx@Wk)^T * d^-0.5) (ctx@Wv) @ Wo + bo
// Shapes: x[2,1024,4,512] -> rows 8192; context[2,2048,512] -> rows 4096;
// Wq[512,512], Wkv[512,1024], Wo[512,512], bo[512]. H=8, D=64, M=2048.
// ---------------------------------------------------------------------------

#define BATCH   2
#define NROWS   8192          // B * N * S
#define CROWS   4096          // B * M
#define QDIM    512
#define INNER   512
#define KVDIM   1024
#define HEADS   8
#define DHEAD   64
#define MCTX    2048

// Scratch (static device allocations are the sanctioned workaround)
__device__ float g_q [NROWS * INNER];    // 16 MB
__device__ float g_kv[CROWS * KVDIM];    // 16 MB
__device__ float g_ao[NROWS * INNER];    // 16 MB

// ---------------------------------------------------------------------------
// Generic fp32 tiled GEMM: C[M,N] = A[M,K] @ B[K,N] (+ bias[n])
// BM=BN=64, BK=16, 256 threads, 4x4 microtile, float4 smem fragments.
// Padding stride 68 floats: column offsets that are multiples of 4 stay
// 16B-aligned for LDS.128 (stride 65 trapped with misaligned address).
// ---------------------------------------------------------------------------
template <bool HAS_BIAS>
__global__ __launch_bounds__(256)
void gemm64(const float* __restrict__ A, const float* __restrict__ B,
            const float* __restrict__ bias, float* __restrict__ C,
            int M, int N, int K)
{
    __shared__ float As[16][68];   // [kk][row]  (transposed on load)
    __shared__ float Bs[16][64];   // [kk][col]

    const int bm  = blockIdx.y * 64;
    const int bn  = blockIdx.x * 64;
    const int tid = threadIdx.x;
    const int tx  = tid & 15;      // 16 col-groups
    const int ty  = tid >> 4;      // 16 row-groups

    float acc[4][4] = {};

    for (int k0 = 0; k0 < K; k0 += 16) {
        #pragma unroll
        for (int i = 0; i < 4; i++) {
            int idx = tid + i * 256;          // 0..1023 over 64x16 A tile
            int kk = idx & 15, row = idx >> 4;
            As[kk][row] = A[(size_t)(bm + row) * K + k0 + kk];
        }
        #pragma unroll
        for (int i = 0; i < 4; i++) {
            int idx = tid + i * 256;          // 0..1023 over 16x64 B tile
            int c = idx & 63, kk = idx >> 6;
            Bs[kk][c] = B[(size_t)(k0 + kk) * N + bn + c];
        }
        __syncthreads();

        #pragma unroll
        for (int kk = 0; kk < 16; kk++) {
            float4 a4 = *(const float4*)&As[kk][ty * 4];
            float4 b4 = *(const float4*)&Bs[kk][tx * 4];
            float av[4] = {a4.x, a4.y, a4.z, a4.w};
            float bv[4] = {b4.x, b4.y, b4.z, b4.w};
            #pragma unroll
            for (int i = 0; i < 4; i++)
                #pragma unroll
                for (int j = 0; j < 4; j++)
                    acc[i][j] += av[i] * bv[j];
        }
        __syncthreads();
    }

    #pragma unroll
    for (int i = 0; i < 4; i++) {
        #pragma unroll
        for (int j = 0; j < 4; j++) {
            float v = acc[i][j];
            if (HAS_BIAS) v += bias[bn + tx * 4 + j];
            C[(size_t)(bm + ty * 4 + i) * N + bn + tx * 4 + j] = v;
        }
    }
}

// ---------------------------------------------------------------------------
// Flash attention, fp32. One block per (batch, head, 64-query tile).
// Q/K stored d-major in smem so QK^T fragments are float4 loads.
// All tile strides are 68 floats (16B-aligned float4 columns).
// ---------------------------------------------------------------------------
#define SM_FLOATS (64*68*4 + 192)

__global__ __launch_bounds__(256)
void attn64(const float* __restrict__ q, const float* __restrict__ kv,
            float* __restrict__ o)
{
    extern __shared__ float sm[];
    float* Qs    = sm;                 // [d][row]   64x68
    float* Ks    = Qs + 64 * 68;       // [d][key]   64x68
    float* Vs    = Ks + 64 * 68;       // [key][d]   64x68
    float* Ps    = Vs + 64 * 68;       // [row][key] 64x68
    float* row_m = Ps + 64 * 68;       // 64
    float* row_l = row_m + 64;         // 64
    float* row_c = row_l + 64;         // 64

    const int bx = blockIdx.x;
    const int qt = bx & 63;
    const int h  = (bx >> 6) & 7;
    const int b  = bx >> 9;

    const int tid = threadIdx.x;
    const int tx  = tid & 15;
    const int ty  = tid >> 4;
    const int r0  = ty * 4;
    const int c0  = tx * 4;

    const float* qbase = q  + (size_t)(b * 4096 + qt * 64) * INNER + h * DHEAD;
    const float* kbase = kv + (size_t)b * MCTX * KVDIM + h * DHEAD;
    const float* vbase = kbase + INNER;   // v half of kv

    // Load Q tile (pre-scaled by d^-0.5), transposed to d-major
    for (int i = tid; i < 4096; i += 256) {
        int r = i >> 6, d = i & 63;
        Qs[d * 68 + r] = qbase[(size_t)r * INNER + d] * 0.125f;
    }
    if (tid < 64) { row_m[tid] = -1e30f; row_l[tid] = 0.0f; }

    float acc[4][4] = {};

    for (int m0 = 0; m0 < MCTX; m0 += 64) {
        __syncthreads();   // previous PV reads of Ps/Vs done; Q load visible
        for (int i = tid; i < 4096; i += 256) {
            int m = i >> 6, d = i & 63;
            size_t roff = (size_t)(m0 + m) * KVDIM + d;
            Ks[d * 68 + m] = kbase[roff];
            Vs[m * 68 + d] = vbase[roff];
        }
        __syncthreads();

        // S = Q K^T (64x64x64)
        float s[4][4] = {};
        #pragma unroll 8
        for (int d = 0; d < 64; d++) {
            float4 qa = *(const float4*)&Qs[d * 68 + r0];
            float4 kb = *(const float4*)&Ks[d * 68 + c0];
            float av[4] = {qa.x, qa.y, qa.z, qa.w};
            float bv[4] = {kb.x, kb.y, kb.z, kb.w};
            #pragma unroll
            for (int i = 0; i < 4; i++)
                #pragma unroll
                for (int j = 0; j < 4; j++)
                    s[i][j] += av[i] * bv[j];
        }
        #pragma unroll
        for (int i = 0; i < 4; i++)
            *(float4*)&Ps[(r0 + i) * 68 + c0] =
                make_float4(s[i][0], s[i][1], s[i][2], s[i][3]);
        __syncthreads();

        // Online softmax, one thread per query row
        if (tid < 64) {
            float* prow = Ps + tid * 68;
            float mold = row_m[tid];
            float mnew = mold;
            #pragma unroll 8
            for (int j = 0; j < 64; j++) mnew = fmaxf(mnew, prow[j]);
            float corr = __expf(mold - mnew);
            float sum = 0.0f;
            #pragma unroll 8
            for (int j = 0; j < 64; j++) {
                float e = __expf(prow[j] - mnew);
                prow[j] = e;
                sum += e;
            }
            row_m[tid] = mnew;
            row_c[tid] = corr;
            row_l[tid] = row_l[tid] * corr + sum;
        }
        __syncthreads();

        // O = O*corr + P @ V
        float cr[4];
        #pragma unroll
        for (int i = 0; i < 4; i++) cr[i] = row_c[r0 + i];
        #pragma unroll
        for (int i = 0; i < 4; i++)
            #pragma unroll
            for (int j = 0; j < 4; j++)
                acc[i][j] *= cr[i];

        #pragma unroll 8
        for (int m = 0; m < 64; m++) {
            float4 vb = *(const float4*)&Vs[m * 68 + c0];
            float bv[4] = {vb.x, vb.y, vb.z, vb.w};
            float pv[4];
            #pragma unroll
            for (int i = 0; i < 4; i++) pv[i] = Ps[(r0 + i) * 68 + m];
            #pragma unroll
            for (int i = 0; i < 4; i++)
                #pragma unroll
                for (int j = 0; j < 4; j++)
                    acc[i][j] += pv[i] * bv[j];
        }
    }

    float* obase = o + (size_t)(b * 4096 + qt * 64) * INNER + h * DHEAD;
    #pragma unroll
    for (int i = 0; i < 4; i++) {
        float inv = 1.0f / row_l[r0 + i];
        #pragma unroll
        for (int j = 0; j < 4; j++)
            obase[(size_t)(r0 + i) * INNER + c0 + j] = acc[i][j] * inv;
    }
}

// ---------------------------------------------------------------------------
extern "C" void kernel_launch(void* const* d_in, const int* in_sizes, int n_in,
                              void* d_out, int out_size)
{
    const float* x   = (const float*)d_in[0];
    const float* ctx = (const float*)d_in[1];
    const float* Wq  = (const float*)d_in[2];
    const float* Wkv = (const float*)d_in[3];
    const float* Wo  = (const float*)d_in[4];
    const float* bo  = (const float*)d_in[5];
    float* out = (float*)d_out;

    float *qp = nullptr, *kvp = nullptr, *aop = nullptr;
    cudaGetSymbolAddress((void**)&qp,  g_q);
    cudaGetSymbolAddress((void**)&kvp, g_kv);
    cudaGetSymbolAddress((void**)&aop, g_ao);

    // Q projection: [8192,512] = x @ Wq
    gemm64<false><<<dim3(INNER / 64, NROWS / 64), 256>>>(
        x, Wq, nullptr, qp, NROWS, INNER, QDIM);

    // KV projection: [4096,1024] = ctx @ Wkv
    gemm64<false><<<dim3(KVDIM / 64, CROWS / 64), 256>>>(
        ctx, Wkv, nullptr, kvp, CROWS, KVDIM, QDIM);

    // Attention: 2 batches x 8 heads x 64 query tiles
    const size_t smem_bytes = SM_FLOATS * sizeof(float);   // ~69.6 KB
    cudaFuncSetAttribute(attn64, cudaFuncAttributeMaxDynamicSharedMemorySize,
                         (int)smem_bytes);
    attn64<<<BATCH * HEADS * 64, 256, smem_bytes>>>(qp, kvp, aop);

    // Output projection + bias
    gemm64<true><<<dim3(INNER / 64, NROWS / 64), 256>>>(
        aop, Wo, bo, out, NROWS, INNER, INNER);
}

// round 5
// speedup vs baseline: 2.0302x; 2.0298x over previous
#include <cuda_runtime.h>
#include <cuda_bf16.h>
#include <cstdint>
#include <cstddef>

#define NROWS 8192
#define CROWS 4096
#define QDIM  512
#define INNER 512
#define KVDIM 1024
#define MCTX  2048

typedef __nv_bfloat16 bf16;

// ---------------- static scratch (bf16 hi/lo) -------------------------------
__device__ __align__(256) bf16 g_xh [NROWS * QDIM],  g_xl [NROWS * QDIM];
__device__ __align__(256) bf16 g_ch [CROWS * QDIM],  g_cl [CROWS * QDIM];
__device__ __align__(256) bf16 g_wqh[INNER * QDIM],  g_wql[INNER * QDIM];
__device__ __align__(256) bf16 g_wkh[KVDIM * QDIM],  g_wkl[KVDIM * QDIM];
__device__ __align__(256) bf16 g_woh[INNER * INNER], g_wol[INNER * INNER];
__device__ __align__(256) bf16 g_qh [NROWS * INNER], g_ql [NROWS * INNER];
__device__ __align__(256) bf16 g_kvh[CROWS * KVDIM], g_kvl[CROWS * KVDIM];
__device__ __align__(256) bf16 g_aoh[NROWS * INNER], g_aol[NROWS * INNER];

// ---------------- helpers ----------------------------------------------------
#define SWZ(off) ((off) ^ (((off) >> 3) & 0x70))

static __device__ __forceinline__ uint32_t smem_u32(const void* p) {
    uint32_t a;
    asm("{ .reg .u64 t; cvta.to.shared.u64 t, %1; cvt.u32.u64 %0, t; }"
        : "=r"(a) : "l"(p));
    return a;
}
static __device__ __forceinline__ void ldsm4(uint32_t& r0, uint32_t& r1,
                                             uint32_t& r2, uint32_t& r3, uint32_t a) {
    asm volatile("ldmatrix.sync.aligned.m8n8.x4.shared.b16 {%0,%1,%2,%3}, [%4];"
                 : "=r"(r0), "=r"(r1), "=r"(r2), "=r"(r3) : "r"(a));
}
static __device__ __forceinline__ void mma16816(float* c, const uint32_t* a,
                                                uint32_t b0, uint32_t b1) {
    asm volatile("mma.sync.aligned.m16n8k16.row.col.f32.bf16.bf16.f32 "
                 "{%0,%1,%2,%3}, {%4,%5,%6,%7}, {%8,%9}, {%0,%1,%2,%3};"
                 : "+f"(c[0]), "+f"(c[1]), "+f"(c[2]), "+f"(c[3])
                 : "r"(a[0]), "r"(a[1]), "r"(a[2]), "r"(a[3]), "r"(b0), "r"(b1));
}
static __device__ __forceinline__ uint32_t packbf(float a, float b) {
    __nv_bfloat162 t = __floats2bfloat162_rn(a, b);
    return *(uint32_t*)&t;
}

// ---------------- conversion kernels -----------------------------------------
__global__ void split_plain(const float* __restrict__ in, bf16* __restrict__ oh,
                            bf16* __restrict__ ol, int n) {
    int i = blockIdx.x * 256 + threadIdx.x;
    if (i < n) {
        float v = in[i];
        bf16 h = __float2bfloat16(v);
        oh[i] = h;
        ol[i] = __float2bfloat16(v - __bfloat162float(h));
    }
}
__global__ void split_transpose(const float* __restrict__ in, bf16* __restrict__ oh,
                                bf16* __restrict__ ol, int K, int N) {
    int i = blockIdx.x * 256 + threadIdx.x;
    if (i < K * N) {
        int k = i / N, n = i - k * N;
        float v = in[i];
        bf16 h = __float2bfloat16(v);
        size_t o = (size_t)n * K + k;
        oh[o] = h;
        ol[o] = __float2bfloat16(v - __bfloat162float(h));
    }
}

// ---------------- HMMA GEMM: C[M,N] = A[M,K] @ Bt[N,K]^T ---------------------
// 128x128 block, 8 warps (2x4), warp tile 64x32, 3-term bf16 split.
template <int MODE>   // 0: bf16 hi/lo out; 1: fp32 + bias out
__global__ __launch_bounds__(256, 2)
void mm_gemm(const bf16* __restrict__ ah, const bf16* __restrict__ al,
             const bf16* __restrict__ bth, const bf16* __restrict__ btl,
             bf16* __restrict__ coh, bf16* __restrict__ col_,
             float* __restrict__ cf, const float* __restrict__ bias,
             int M, int N, int K)
{
    __shared__ __align__(128) char smA[16384];
    __shared__ __align__(128) char smB[16384];
    const uint32_t sA = smem_u32(smA), sB = smem_u32(smB);

    const int tid = threadIdx.x, warp = tid >> 5, lane = tid & 31;
    const int wm = warp >> 2, wn = warp & 3;
    const int bm = blockIdx.y * 128, bn = blockIdx.x * 128;

    float c[4][4][4] = {};

    // precomputed ldmatrix lane offsets
    const int a_row = (lane & 15), a_cb = (lane >> 4) * 16;
    const int b_row = (lane & 7) + (lane >> 4) * 8, b_cb = ((lane >> 3) & 1) * 16;

    for (int term = 0; term < 3; term++) {
        const bf16* A = (term == 1) ? al : ah;
        const bf16* B = (term == 2) ? btl : bth;
        for (int k0 = 0; k0 < K; k0 += 64) {
            __syncthreads();
            #pragma unroll
            for (int i = 0; i < 4; i++) {
                int idx = tid + i * 256;
                int r = idx >> 3, cc = idx & 7;
                *(uint4*)(smA + SWZ(r * 128 + cc * 16)) =
                    *(const uint4*)(A + (size_t)(bm + r) * K + k0 + cc * 8);
                *(uint4*)(smB + SWZ(r * 128 + cc * 16)) =
                    *(const uint4*)(B + (size_t)(bn + r) * K + k0 + cc * 8);
            }
            __syncthreads();

            #pragma unroll
            for (int ks = 0; ks < 4; ks++) {
                uint32_t af[4][4], bfr[4][2];
                #pragma unroll
                for (int mt = 0; mt < 4; mt++) {
                    int row = wm * 64 + mt * 16 + a_row;
                    ldsm4(af[mt][0], af[mt][1], af[mt][2], af[mt][3],
                          sA + SWZ(row * 128 + ks * 32 + a_cb));
                }
                #pragma unroll
                for (int np = 0; np < 2; np++) {
                    int row = wn * 32 + np * 16 + b_row;
                    uint32_t r0, r1, r2, r3;
                    ldsm4(r0, r1, r2, r3, sB + SWZ(row * 128 + ks * 32 + b_cb));
                    bfr[np*2][0] = r0; bfr[np*2][1] = r1;
                    bfr[np*2+1][0] = r2; bfr[np*2+1][1] = r3;
                }
                #pragma unroll
                for (int mt = 0; mt < 4; mt++)
                    #pragma unroll
                    for (int nt = 0; nt < 4; nt++)
                        mma16816(c[mt][nt], af[mt], bfr[nt][0], bfr[nt][1]);
            }
        }
    }

    // epilogue
    #pragma unroll
    for (int mt = 0; mt < 4; mt++) {
        int row0 = bm + wm * 64 + mt * 16 + (lane >> 2);
        #pragma unroll
        for (int nt = 0; nt < 4; nt++) {
            int col = bn + wn * 32 + nt * 8 + (lane & 3) * 2;
            float v0 = c[mt][nt][0], v1 = c[mt][nt][1];
            float v2 = c[mt][nt][2], v3 = c[mt][nt][3];
            if (MODE == 0) {
                uint32_t h01 = packbf(v0, v1), h23 = packbf(v2, v3);
                __nv_bfloat162 H01 = *(__nv_bfloat162*)&h01, H23 = *(__nv_bfloat162*)&h23;
                uint32_t l01 = packbf(v0 - __low2float(H01), v1 - __high2float(H01));
                uint32_t l23 = packbf(v2 - __low2float(H23), v3 - __high2float(H23));
                *(uint32_t*)(coh  + (size_t)row0 * N + col)       = h01;
                *(uint32_t*)(coh  + (size_t)(row0 + 8) * N + col) = h23;
                *(uint32_t*)(col_ + (size_t)row0 * N + col)       = l01;
                *(uint32_t*)(col_ + (size_t)(row0 + 8) * N + col) = l23;
            } else {
                float b0 = bias[col], b1 = bias[col + 1];
                *(float2*)(cf + (size_t)row0 * N + col)       = make_float2(v0 + b0, v1 + b1);
                *(float2*)(cf + (size_t)(row0 + 8) * N + col) = make_float2(v2 + b0, v3 + b1);
            }
        }
    }
}

// ---------------- HMMA flash attention ---------------------------------------
// Block = (b, h, 128-q tile), 256 threads = 8 warps: wm=warp>>1 (32 rows each),
// wn=warp&1 (64-key half). 16 chunks of 128 keys. No max-subtraction.
#define AQ_H 0
#define AQ_L 16384
#define AK_H 32768
#define AK_L 49152
#define AV_B 65536           // 4 x [64][64] tiles: VH0 VH1 VL0 VL1 (8KB each)
#define ALBUF 98304          // 2 x 128 floats
#define A_SM_TOTAL 99328

__global__ __launch_bounds__(256, 1)
void mm_attn(const bf16* __restrict__ qh, const bf16* __restrict__ ql,
             const bf16* __restrict__ kvh, const bf16* __restrict__ kvl,
             bf16* __restrict__ aoh, bf16* __restrict__ aol)
{
    extern __shared__ __align__(128) char sm[];
    const uint32_t sbase = smem_u32(sm);

    const int tid = threadIdx.x, warp = tid >> 5, lane = tid & 31;
    const int wm = warp >> 1, wn = warp & 1;
    const int bx = blockIdx.x;
    const int qt = bx & 31, h = (bx >> 5) & 7, b = bx >> 8;

    const bf16* qbh = qh + (size_t)(b * 4096 + qt * 128) * INNER + h * 64;
    const bf16* qbl = ql + (size_t)(b * 4096 + qt * 128) * INNER + h * 64;
    const bf16* kbh = kvh + (size_t)(b * MCTX) * KVDIM + h * 64;
    const bf16* kbl = kvl + (size_t)(b * MCTX) * KVDIM + h * 64;

    // Q tiles (persistent)
    #pragma unroll
    for (int i = 0; i < 4; i++) {
        int idx = tid + i * 256;
        int r = idx >> 3, cc = idx & 7;
        uint32_t so = SWZ(r * 128 + cc * 16);
        *(uint4*)(sm + AQ_H + so) = *(const uint4*)(qbh + (size_t)r * INNER + cc * 8);
        *(uint4*)(sm + AQ_L + so) = *(const uint4*)(qbl + (size_t)r * INNER + cc * 8);
    }

    const int a_row = (lane & 15), a_cb = (lane >> 4) * 16;
    const int b_row = (lane & 7) + (lane >> 4) * 8, b_cb = ((lane >> 3) & 1) * 16;

    float o[2][8][4] = {};
    float lp[2][2] = {};

    for (int it = 0; it < 16; it++) {
        __syncthreads();
        // K chunk hi/lo
        #pragma unroll
        for (int i = 0; i < 4; i++) {
            int idx = tid + i * 256;
            int r = idx >> 3, cc = idx & 7;
            size_t g = (size_t)(it * 128 + r) * KVDIM + cc * 8;
            uint32_t so = SWZ(r * 128 + cc * 16);
            *(uint4*)(sm + AK_H + so) = *(const uint4*)(kbh + g);
            *(uint4*)(sm + AK_L + so) = *(const uint4*)(kbl + g);
        }
        // V chunk transposed -> [d][key] half-tiles
        #pragma unroll
        for (int i = 0; i < 4; i++) {
            int idx = tid + i * 256;
            int key = idx >> 3, dg = idx & 7;
            size_t g = INNER + (size_t)(it * 128 + key) * KVDIM + dg * 8;
            uint4 wh = *(const uint4*)(kbh + g);
            uint4 wl = *(const uint4*)(kbl + g);
            const bf16* eh = (const bf16*)&wh;
            const bf16* el = (const bf16*)&wl;
            char* th = sm + AV_B + (key >> 6) * 8192;
            char* tl = th + 16384;
            #pragma unroll
            for (int t = 0; t < 8; t++) {
                uint32_t off = SWZ((dg * 8 + t) * 128 + (key & 63) * 2);
                *(bf16*)(th + off) = eh[t];
                *(bf16*)(tl + off) = el[t];
            }
        }
        __syncthreads();

        // ---- S = Q K^T (3 terms) ----
        float s[2][8][4] = {};
        #pragma unroll
        for (int ks = 0; ks < 4; ks++) {
            uint32_t ah2[2][4], al2[2][4], bh2[8][2], bl2[8][2];
            #pragma unroll
            for (int mt = 0; mt < 2; mt++) {
                int row = wm * 32 + mt * 16 + a_row;
                uint32_t so = SWZ(row * 128 + ks * 32 + a_cb);
                ldsm4(ah2[mt][0], ah2[mt][1], ah2[mt][2], ah2[mt][3], sbase + AQ_H + so);
                ldsm4(al2[mt][0], al2[mt][1], al2[mt][2], al2[mt][3], sbase + AQ_L + so);
            }
            #pragma unroll
            for (int np = 0; np < 4; np++) {
                int row = wn * 64 + np * 16 + b_row;
                uint32_t so = SWZ(row * 128 + ks * 32 + b_cb);
                uint32_t r0, r1, r2, r3;
                ldsm4(r0, r1, r2, r3, sbase + AK_H + so);
                bh2[np*2][0] = r0; bh2[np*2][1] = r1;
                bh2[np*2+1][0] = r2; bh2[np*2+1][1] = r3;
                ldsm4(r0, r1, r2, r3, sbase + AK_L + so);
                bl2[np*2][0] = r0; bl2[np*2][1] = r1;
                bl2[np*2+1][0] = r2; bl2[np*2+1][1] = r3;
            }
            #pragma unroll
            for (int mt = 0; mt < 2; mt++)
                #pragma unroll
                for (int nt = 0; nt < 8; nt++) {
                    mma16816(s[mt][nt], ah2[mt], bh2[nt][0], bh2[nt][1]);
                    mma16816(s[mt][nt], al2[mt], bh2[nt][0], bh2[nt][1]);
                    mma16816(s[mt][nt], ah2[mt], bl2[nt][0], bl2[nt][1]);
                }
        }

        // ---- exp + pack P hi/lo as A-fragments (C-frag == A-frag layout) ----
        uint32_t pa[2][4][4], pl[2][4][4];
        #pragma unroll
        for (int mt = 0; mt < 2; mt++)
            #pragma unroll
            for (int ks2 = 0; ks2 < 4; ks2++)
                #pragma unroll
                for (int jj = 0; jj < 2; jj++) {
                    float* sv = s[mt][2 * ks2 + jj];
                    float e0 = __expf(sv[0] * 0.125f), e1 = __expf(sv[1] * 0.125f);
                    float e2 = __expf(sv[2] * 0.125f), e3 = __expf(sv[3] * 0.125f);
                    lp[mt][0] += e0 + e1;
                    lp[mt][1] += e2 + e3;
                    uint32_t h01 = packbf(e0, e1), h23 = packbf(e2, e3);
                    __nv_bfloat162 H01 = *(__nv_bfloat162*)&h01;
                    __nv_bfloat162 H23 = *(__nv_bfloat162*)&h23;
                    pa[mt][ks2][jj * 2]     = h01;
                    pa[mt][ks2][jj * 2 + 1] = h23;
                    pl[mt][ks2][jj * 2]     = packbf(e0 - __low2float(H01),
                                                     e1 - __high2float(H01));
                    pl[mt][ks2][jj * 2 + 1] = packbf(e2 - __low2float(H23),
                                                     e3 - __high2float(H23));
                }

        // ---- O += P V (3 terms), V from this warp's key half ----
        const uint32_t vh = sbase + AV_B + wn * 8192;
        const uint32_t vl = vh + 16384;
        #pragma unroll
        for (int ks2 = 0; ks2 < 4; ks2++) {
            uint32_t bh2[8][2], bl2[8][2];
            #pragma unroll
            for (int np = 0; np < 4; np++) {
                int row = np * 16 + b_row;
                uint32_t so = SWZ(row * 128 + ks2 * 32 + b_cb);
                uint32_t r0, r1, r2, r3;
                ldsm4(r0, r1, r2, r3, vh + so);
                bh2[np*2][0] = r0; bh2[np*2][1] = r1;
                bh2[np*2+1][0] = r2; bh2[np*2+1][1] = r3;
                ldsm4(r0, r1, r2, r3, vl + so);
                bl2[np*2][0] = r0; bl2[np*2][1] = r1;
                bl2[np*2+1][0] = r2; bl2[np*2+1][1] = r3;
            }
            #pragma unroll
            for (int mt = 0; mt < 2; mt++)
                #pragma unroll
                for (int dt = 0; dt < 8; dt++) {
                    mma16816(o[mt][dt], pa[mt][ks2], bh2[dt][0], bh2[dt][1]);
                    mma16816(o[mt][dt], pl[mt][ks2], bh2[dt][0], bh2[dt][1]);
                    mma16816(o[mt][dt], pa[mt][ks2], bl2[dt][0], bl2[dt][1]);
                }
        }
    }

    // ---- l reduce: quad shuffle, then per-wn smem ----
    float* lbuf = (float*)(sm + ALBUF);
    #pragma unroll
    for (int mt = 0; mt < 2; mt++)
        #pragma unroll
        for (int rr = 0; rr < 2; rr++) {
            float v = lp[mt][rr];
            v += __shfl_xor_sync(0xFFFFFFFF, v, 1);
            v += __shfl_xor_sync(0xFFFFFFFF, v, 2);
            if ((lane & 3) == 0)
                lbuf[wn * 128 + wm * 32 + mt * 16 + rr * 8 + (lane >> 2)] = v;
        }
    __syncthreads();

    // ---- O reduce across wn via smem (reuse Q region) ----
    float* obuf = (float*)sm;
    if (wn == 1) {
        #pragma unroll
        for (int mt = 0; mt < 2; mt++) {
            int r0 = wm * 32 + mt * 16 + (lane >> 2);
            #pragma unroll
            for (int dt = 0; dt < 8; dt++) {
                int col = dt * 8 + (lane & 3) * 2;
                *(float2*)(obuf + r0 * 64 + col) = make_float2(o[mt][dt][0], o[mt][dt][1]);
                *(float2*)(obuf + (r0 + 8) * 64 + col) = make_float2(o[mt][dt][2], o[mt][dt][3]);
            }
        }
    }
    __syncthreads();
    if (wn == 0) {
        #pragma unroll
        for (int mt = 0; mt < 2; mt++) {
            int r0 = wm * 32 + mt * 16 + (lane >> 2);
            int r1 = r0 + 8;
            float inv0 = 1.0f / (lbuf[r0] + lbuf[128 + r0]);
            float inv1 = 1.0f / (lbuf[r1] + lbuf[128 + r1]);
            #pragma unroll
            for (int dt = 0; dt < 8; dt++) {
                int col = dt * 8 + (lane & 3) * 2;
                float2 p0 = *(float2*)(obuf + r0 * 64 + col);
                float2 p1 = *(float2*)(obuf + r1 * 64 + col);
                float v0 = (o[mt][dt][0] + p0.x) * inv0;
                float v1 = (o[mt][dt][1] + p0.y) * inv0;
                float v2 = (o[mt][dt][2] + p1.x) * inv1;
                float v3 = (o[mt][dt][3] + p1.y) * inv1;
                uint32_t h01 = packbf(v0, v1), h23 = packbf(v2, v3);
                __nv_bfloat162 H01 = *(__nv_bfloat162*)&h01, H23 = *(__nv_bfloat162*)&h23;
                uint32_t l01 = packbf(v0 - __low2float(H01), v1 - __high2float(H01));
                uint32_t l23 = packbf(v2 - __low2float(H23), v3 - __high2float(H23));
                size_t g0 = (size_t)(b * 4096 + qt * 128 + r0) * INNER + h * 64 + col;
                size_t g1 = (size_t)(b * 4096 + qt * 128 + r1) * INNER + h * 64 + col;
                *(uint32_t*)(aoh + g0) = h01;
                *(uint32_t*)(aoh + g1) = h23;
                *(uint32_t*)(aol + g0) = l01;
                *(uint32_t*)(aol + g1) = l23;
            }
        }
    }
}

// ---------------------------------------------------------------------------
extern "C" void kernel_launch(void* const* d_in, const int* in_sizes, int n_in,
                              void* d_out, int out_size)
{
    const float* x   = (const float*)d_in[0];
    const float* ctx = (const float*)d_in[1];
    const float* Wq  = (const float*)d_in[2];
    const float* Wkv = (const float*)d_in[3];
    const float* Wo  = (const float*)d_in[4];
    const float* bo  = (const float*)d_in[5];
    float* out = (float*)d_out;

    bf16 *xh, *xl, *ch, *cl, *wqh, *wql, *wkh, *wkl, *woh, *wol;
    bf16 *qh2, *ql2, *kvh, *kvl, *aoh, *aol;
    cudaGetSymbolAddress((void**)&xh,  g_xh);  cudaGetSymbolAddress((void**)&xl,  g_xl);
    cudaGetSymbolAddress((void**)&ch,  g_ch);  cudaGetSymbolAddress((void**)&cl,  g_cl);
    cudaGetSymbolAddress((void**)&wqh, g_wqh); cudaGetSymbolAddress((void**)&wql, g_wql);
    cudaGetSymbolAddress((void**)&wkh, g_wkh); cudaGetSymbolAddress((void**)&wkl, g_wkl);
    cudaGetSymbolAddress((void**)&woh, g_woh); cudaGetSymbolAddress((void**)&wol, g_wol);
    cudaGetSymbolAddress((void**)&qh2, g_qh);  cudaGetSymbolAddress((void**)&ql2, g_ql);
    cudaGetSymbolAddress((void**)&kvh, g_kvh); cudaGetSymbolAddress((void**)&kvl, g_kvl);
    cudaGetSymbolAddress((void**)&aoh, g_aoh); cudaGetSymbolAddress((void**)&aol, g_aol);

    cudaFuncSetAttribute(mm_attn, cudaFuncAttributeMaxDynamicSharedMemorySize, A_SM_TOTAL);

    int n1 = NROWS * QDIM, n2 = CROWS * QDIM;
    split_plain<<<(n1 + 255) / 256, 256>>>(x, xh, xl, n1);
    split_plain<<<(n2 + 255) / 256, 256>>>(ctx, ch, cl, n2);
    split_transpose<<<(QDIM * INNER + 255) / 256, 256>>>(Wq,  wqh, wql, QDIM, INNER);
    split_transpose<<<(QDIM * KVDIM + 255) / 256, 256>>>(Wkv, wkh, wkl, QDIM, KVDIM);
    split_transpose<<<(INNER * INNER + 255) / 256, 256>>>(Wo, woh, wol, INNER, INNER);

    mm_gemm<0><<<dim3(INNER / 128, NROWS / 128), 256>>>(
        xh, xl, wqh, wql, qh2, ql2, nullptr, nullptr, NROWS, INNER, QDIM);
    mm_gemm<0><<<dim3(KVDIM / 128, CROWS / 128), 256>>>(
        ch, cl, wkh, wkl, kvh, kvl, nullptr, nullptr, CROWS, KVDIM, QDIM);

    mm_attn<<<512, 256, A_SM_TOTAL>>>(qh2, ql2, kvh, kvl, aoh, aol);

    mm_gemm<1><<<dim3(INNER / 128, NROWS / 128), 256>>>(
        aoh, aol, woh, wol, nullptr, nullptr, out, bo, NROWS, INNER, INNER);
}

// round 6
// speedup vs baseline: 3.3927x; 1.6711x over previous
#include <cuda_runtime.h>
#include <cuda_bf16.h>
#include <cstdint>
#include <cstddef>

#define NROWS 8192
#define CROWS 4096
#define QDIM  512
#define INNER 512
#define KVDIM 1024
#define MCTX  2048

typedef __nv_bfloat16 bf16;

// ---------------- static scratch (bf16 hi/lo) -------------------------------
__device__ __align__(256) bf16 g_xh [NROWS * QDIM],  g_xl [NROWS * QDIM];
__device__ __align__(256) bf16 g_ch [CROWS * QDIM],  g_cl [CROWS * QDIM];
__device__ __align__(256) bf16 g_wqh[INNER * QDIM],  g_wql[INNER * QDIM];
__device__ __align__(256) bf16 g_wkh[KVDIM * QDIM],  g_wkl[KVDIM * QDIM];
__device__ __align__(256) bf16 g_woh[INNER * INNER], g_wol[INNER * INNER];
__device__ __align__(256) bf16 g_qh [NROWS * INNER], g_ql [NROWS * INNER];
__device__ __align__(256) bf16 g_kvh[CROWS * KVDIM], g_kvl[CROWS * KVDIM];
__device__ __align__(256) bf16 g_aoh[NROWS * INNER], g_aol[NROWS * INNER];

// ---------------- helpers ----------------------------------------------------
#define SWZ(off) ((off) ^ (((off) >> 3) & 0x70))

static __device__ __forceinline__ uint32_t smem_u32(const void* p) {
    uint32_t a;
    asm("{ .reg .u64 t; cvta.to.shared.u64 t, %1; cvt.u32.u64 %0, t; }"
        : "=r"(a) : "l"(p));
    return a;
}
static __device__ __forceinline__ void ldsm4(uint32_t& r0, uint32_t& r1,
                                             uint32_t& r2, uint32_t& r3, uint32_t a) {
    asm volatile("ldmatrix.sync.aligned.m8n8.x4.shared.b16 {%0,%1,%2,%3}, [%4];"
                 : "=r"(r0), "=r"(r1), "=r"(r2), "=r"(r3) : "r"(a));
}
static __device__ __forceinline__ void ldsm4t(uint32_t& r0, uint32_t& r1,
                                              uint32_t& r2, uint32_t& r3, uint32_t a) {
    asm volatile("ldmatrix.sync.aligned.m8n8.x4.trans.shared.b16 {%0,%1,%2,%3}, [%4];"
                 : "=r"(r0), "=r"(r1), "=r"(r2), "=r"(r3) : "r"(a));
}
static __device__ __forceinline__ void mma16816(float* c, const uint32_t* a,
                                                uint32_t b0, uint32_t b1) {
    asm volatile("mma.sync.aligned.m16n8k16.row.col.f32.bf16.bf16.f32 "
                 "{%0,%1,%2,%3}, {%4,%5,%6,%7}, {%8,%9}, {%0,%1,%2,%3};"
                 : "+f"(c[0]), "+f"(c[1]), "+f"(c[2]), "+f"(c[3])
                 : "r"(a[0]), "r"(a[1]), "r"(a[2]), "r"(a[3]), "r"(b0), "r"(b1));
}
static __device__ __forceinline__ uint32_t packbf(float a, float b) {
    __nv_bfloat162 t = __floats2bfloat162_rn(a, b);
    return *(uint32_t*)&t;
}
#define CP_ASYNC(dst, src) \
    asm volatile("cp.async.cg.shared.global [%0], [%1], 16;" \
                 :: "r"(dst), "l"(src) : "memory")
#define CP_COMMIT() asm volatile("cp.async.commit_group;" ::: "memory")
#define CP_WAIT(n)  asm volatile("cp.async.wait_group %0;" :: "n"(n) : "memory")

// ---------------- conversion kernels -----------------------------------------
__global__ void split_plain4(const float4* __restrict__ in, uint2* __restrict__ oh,
                             uint2* __restrict__ ol, int n4) {
    int i = blockIdx.x * 256 + threadIdx.x;
    if (i < n4) {
        float4 v = in[i];
        uint32_t h0 = packbf(v.x, v.y), h1 = packbf(v.z, v.w);
        __nv_bfloat162 H0 = *(__nv_bfloat162*)&h0, H1 = *(__nv_bfloat162*)&h1;
        uint32_t l0 = packbf(v.x - __low2float(H0), v.y - __high2float(H0));
        uint32_t l1 = packbf(v.z - __low2float(H1), v.w - __high2float(H1));
        oh[i] = make_uint2(h0, h1);
        ol[i] = make_uint2(l0, l1);
    }
}

// W[K,N] fp32 -> Wt[N,K] bf16 hi/lo, 64k x 32n tiles through smem
__global__ __launch_bounds__(256)
void split_transpose_t(const float* __restrict__ in, bf16* __restrict__ oh,
                       bf16* __restrict__ ol, int K, int N) {
    __shared__ float t[64][33];
    const int tid = threadIdx.x, tx = tid & 31, ty = tid >> 5;
    const int k0 = blockIdx.y * 64, n0 = blockIdx.x * 32;
    #pragma unroll
    for (int r = ty; r < 64; r += 8)
        t[r][tx] = in[(size_t)(k0 + r) * N + n0 + tx];
    __syncthreads();
    #pragma unroll
    for (int r = ty; r < 32; r += 8) {
        int n = n0 + r;
        float v0 = t[tx * 2][r], v1 = t[tx * 2 + 1][r];
        uint32_t h = packbf(v0, v1);
        __nv_bfloat162 H = *(__nv_bfloat162*)&h;
        uint32_t l = packbf(v0 - __low2float(H), v1 - __high2float(H));
        *(uint32_t*)(oh + (size_t)n * K + k0 + tx * 2) = h;
        *(uint32_t*)(ol + (size_t)n * K + k0 + tx * 2) = l;
    }
}

// ---------------- HMMA GEMM: C[M,N] = A[M,K] @ Bt[N,K]^T ---------------------
// 128x128 block, 8 warps (2x4), warp tile 64x32.
// Term-inner: load Ah/Al/Bh/Bl per 64-chunk once, 3 MMA passes.
#define G_AH 0
#define G_AL 16384
#define G_BH 32768
#define G_BL 49152
#define G_SM_TOTAL 65536

template <int MODE>   // 0: bf16 hi/lo out; 1: fp32 + bias out
__global__ __launch_bounds__(256, 2)
void mm_gemm(const bf16* __restrict__ ah, const bf16* __restrict__ al,
             const bf16* __restrict__ bth, const bf16* __restrict__ btl,
             bf16* __restrict__ coh, bf16* __restrict__ col_,
             float* __restrict__ cf, const float* __restrict__ bias,
             int M, int N, int K)
{
    extern __shared__ __align__(128) char sm[];
    const uint32_t sbase = smem_u32(sm);

    const int tid = threadIdx.x, warp = tid >> 5, lane = tid & 31;
    const int wm = warp >> 2, wn = warp & 3;
    const int bm = blockIdx.y * 128, bn = blockIdx.x * 128;

    float c[4][4][4] = {};

    const int a_row = (lane & 15), a_cb = (lane >> 4) * 16;
    const int b_row = (lane & 7) + (lane >> 4) * 8, b_cb = ((lane >> 3) & 1) * 16;

    for (int k0 = 0; k0 < K; k0 += 64) {
        __syncthreads();
        #pragma unroll
        for (int i = 0; i < 4; i++) {
            int idx = tid + i * 256;
            int r = idx >> 3, cc = idx & 7;
            uint32_t off = SWZ(r * 128 + cc * 16);
            size_t ga = (size_t)(bm + r) * K + k0 + cc * 8;
            size_t gb = (size_t)(bn + r) * K + k0 + cc * 8;
            CP_ASYNC(sbase + G_AH + off, ah + ga);
            CP_ASYNC(sbase + G_AL + off, al + ga);
            CP_ASYNC(sbase + G_BH + off, bth + gb);
            CP_ASYNC(sbase + G_BL + off, btl + gb);
        }
        CP_COMMIT();
        CP_WAIT(0);
        __syncthreads();

        #pragma unroll
        for (int ks = 0; ks < 4; ks++) {
            uint32_t afh[4][4], afl[4][4], bfr[4][2];
            #pragma unroll
            for (int mt = 0; mt < 4; mt++) {
                int row = wm * 64 + mt * 16 + a_row;
                uint32_t so = SWZ(row * 128 + ks * 32 + a_cb);
                ldsm4(afh[mt][0], afh[mt][1], afh[mt][2], afh[mt][3], sbase + G_AH + so);
                ldsm4(afl[mt][0], afl[mt][1], afl[mt][2], afl[mt][3], sbase + G_AL + so);
            }
            // pass 1+2: (Ah + Al) * Bh
            #pragma unroll
            for (int np = 0; np < 2; np++) {
                int row = wn * 32 + np * 16 + b_row;
                uint32_t r0, r1, r2, r3;
                ldsm4(r0, r1, r2, r3, sbase + G_BH + SWZ(row * 128 + ks * 32 + b_cb));
                bfr[np*2][0] = r0; bfr[np*2][1] = r1;
                bfr[np*2+1][0] = r2; bfr[np*2+1][1] = r3;
            }
            #pragma unroll
            for (int mt = 0; mt < 4; mt++)
                #pragma unroll
                for (int nt = 0; nt < 4; nt++) {
                    mma16816(c[mt][nt], afh[mt], bfr[nt][0], bfr[nt][1]);
                    mma16816(c[mt][nt], afl[mt], bfr[nt][0], bfr[nt][1]);
                }
            // pass 3: Ah * Bl
            #pragma unroll
            for (int np = 0; np < 2; np++) {
                int row = wn * 32 + np * 16 + b_row;
                uint32_t r0, r1, r2, r3;
                ldsm4(r0, r1, r2, r3, sbase + G_BL + SWZ(row * 128 + ks * 32 + b_cb));
                bfr[np*2][0] = r0; bfr[np*2][1] = r1;
                bfr[np*2+1][0] = r2; bfr[np*2+1][1] = r3;
            }
            #pragma unroll
            for (int mt = 0; mt < 4; mt++)
                #pragma unroll
                for (int nt = 0; nt < 4; nt++)
                    mma16816(c[mt][nt], afh[mt], bfr[nt][0], bfr[nt][1]);
        }
    }

    // epilogue
    #pragma unroll
    for (int mt = 0; mt < 4; mt++) {
        int row0 = bm + wm * 64 + mt * 16 + (lane >> 2);
        #pragma unroll
        for (int nt = 0; nt < 4; nt++) {
            int col = bn + wn * 32 + nt * 8 + (lane & 3) * 2;
            float v0 = c[mt][nt][0], v1 = c[mt][nt][1];
            float v2 = c[mt][nt][2], v3 = c[mt][nt][3];
            if (MODE == 0) {
                uint32_t h01 = packbf(v0, v1), h23 = packbf(v2, v3);
                __nv_bfloat162 H01 = *(__nv_bfloat162*)&h01, H23 = *(__nv_bfloat162*)&h23;
                uint32_t l01 = packbf(v0 - __low2float(H01), v1 - __high2float(H01));
                uint32_t l23 = packbf(v2 - __low2float(H23), v3 - __high2float(H23));
                *(uint32_t*)(coh  + (size_t)row0 * N + col)       = h01;
                *(uint32_t*)(coh  + (size_t)(row0 + 8) * N + col) = h23;
                *(uint32_t*)(col_ + (size_t)row0 * N + col)       = l01;
                *(uint32_t*)(col_ + (size_t)(row0 + 8) * N + col) = l23;
            } else {
                float b0 = bias[col], b1 = bias[col + 1];
                *(float2*)(cf + (size_t)row0 * N + col)       = make_float2(v0 + b0, v1 + b1);
                *(float2*)(cf + (size_t)(row0 + 8) * N + col) = make_float2(v2 + b0, v3 + b1);
            }
        }
    }
}

// ---------------- HMMA flash attention ---------------------------------------
// Block = (b, h, 128-q tile), 8 warps: wm=warp>>1 (32 q-rows), wn=warp&1
// (64-key half). 16 chunks of 128 keys, cp.async 2-stage pipeline.
// V stored [key][d] (same as K); PV B-operand via ldmatrix.trans.
#define AQ_H 0
#define AQ_L 16384
#define ASTG(s) (32768 + (s) * 65536)     // +0 KH, +16384 KL, +32768 VH, +49152 VL
#define ALBUF 163840
#define A_SM_TOTAL 164864

__global__ __launch_bounds__(256, 1)
void mm_attn(const bf16* __restrict__ qh, const bf16* __restrict__ ql,
             const bf16* __restrict__ kvh, const bf16* __restrict__ kvl,
             bf16* __restrict__ aoh, bf16* __restrict__ aol)
{
    extern __shared__ __align__(128) char sm[];
    const uint32_t sbase = smem_u32(sm);

    const int tid = threadIdx.x, warp = tid >> 5, lane = tid & 31;
    const int wm = warp >> 1, wn = warp & 1;
    const int bx = blockIdx.x;
    const int qt = bx & 31, h = (bx >> 5) & 7, b = bx >> 8;

    const bf16* qbh = qh + (size_t)(b * 4096 + qt * 128) * INNER + h * 64;
    const bf16* qbl = ql + (size_t)(b * 4096 + qt * 128) * INNER + h * 64;
    const bf16* kbh = kvh + (size_t)(b * MCTX) * KVDIM + h * 64;
    const bf16* kbl = kvl + (size_t)(b * MCTX) * KVDIM + h * 64;

    // Q tiles (persistent)
    #pragma unroll
    for (int i = 0; i < 4; i++) {
        int idx = tid + i * 256;
        int r = idx >> 3, cc = idx & 7;
        uint32_t so = SWZ(r * 128 + cc * 16);
        *(uint4*)(sm + AQ_H + so) = *(const uint4*)(qbh + (size_t)r * INNER + cc * 8);
        *(uint4*)(sm + AQ_L + so) = *(const uint4*)(qbl + (size_t)r * INNER + cc * 8);
    }

    // prefetch chunk 0 into stage 0
    #pragma unroll
    for (int i = 0; i < 4; i++) {
        int idx = tid + i * 256;
        int r = idx >> 3, cc = idx & 7;
        uint32_t so = SWZ(r * 128 + cc * 16);
        size_t g = (size_t)r * KVDIM + cc * 8;
        CP_ASYNC(sbase + ASTG(0) +     0 + so, kbh + g);
        CP_ASYNC(sbase + ASTG(0) + 16384 + so, kbl + g);
        CP_ASYNC(sbase + ASTG(0) + 32768 + so, kbh + INNER + g);
        CP_ASYNC(sbase + ASTG(0) + 49152 + so, kbl + INNER + g);
    }
    CP_COMMIT();

    const int a_row = (lane & 15), a_cb = (lane >> 4) * 16;
    const int b_row = (lane & 7) + (lane >> 4) * 8, b_cb = ((lane >> 3) & 1) * 16;
    const int v_row = (lane & 7) + ((lane >> 3) & 1) * 8, v_cb = (lane >> 4) * 16;

    float o[2][8][4] = {};
    float lp[2][2] = {};

    for (int it = 0; it < 16; it++) {
        if (it < 15) {
            const uint32_t st = sbase + ASTG((it + 1) & 1);
            #pragma unroll
            for (int i = 0; i < 4; i++) {
                int idx = tid + i * 256;
                int r = idx >> 3, cc = idx & 7;
                uint32_t so = SWZ(r * 128 + cc * 16);
                size_t g = (size_t)((it + 1) * 128 + r) * KVDIM + cc * 8;
                CP_ASYNC(st +     0 + so, kbh + g);
                CP_ASYNC(st + 16384 + so, kbl + g);
                CP_ASYNC(st + 32768 + so, kbh + INNER + g);
                CP_ASYNC(st + 49152 + so, kbl + INNER + g);
            }
            CP_COMMIT();
            CP_WAIT(1);
        } else {
            CP_WAIT(0);
        }
        __syncthreads();

        const uint32_t kh_s = sbase + ASTG(it & 1);
        const uint32_t kl_s = kh_s + 16384;
        const uint32_t vh_s = kh_s + 32768;
        const uint32_t vl_s = kh_s + 49152;

        // ---- S = Q K^T (3 terms) ----
        float s[2][8][4] = {};
        #pragma unroll
        for (int ks = 0; ks < 4; ks++) {
            uint32_t ah2[2][4], al2[2][4], bh2[8][2], bl2[8][2];
            #pragma unroll
            for (int mt = 0; mt < 2; mt++) {
                int row = wm * 32 + mt * 16 + a_row;
                uint32_t so = SWZ(row * 128 + ks * 32 + a_cb);
                ldsm4(ah2[mt][0], ah2[mt][1], ah2[mt][2], ah2[mt][3], sbase + AQ_H + so);
                ldsm4(al2[mt][0], al2[mt][1], al2[mt][2], al2[mt][3], sbase + AQ_L + so);
            }
            #pragma unroll
            for (int np = 0; np < 4; np++) {
                int row = wn * 64 + np * 16 + b_row;
                uint32_t so = SWZ(row * 128 + ks * 32 + b_cb);
                uint32_t r0, r1, r2, r3;
                ldsm4(r0, r1, r2, r3, kh_s + so);
                bh2[np*2][0] = r0; bh2[np*2][1] = r1;
                bh2[np*2+1][0] = r2; bh2[np*2+1][1] = r3;
                ldsm4(r0, r1, r2, r3, kl_s + so);
                bl2[np*2][0] = r0; bl2[np*2][1] = r1;
                bl2[np*2+1][0] = r2; bl2[np*2+1][1] = r3;
            }
            #pragma unroll
            for (int mt = 0; mt < 2; mt++)
                #pragma unroll
                for (int nt = 0; nt < 8; nt++) {
                    mma16816(s[mt][nt], ah2[mt], bh2[nt][0], bh2[nt][1]);
                    mma16816(s[mt][nt], al2[mt], bh2[nt][0], bh2[nt][1]);
                    mma16816(s[mt][nt], ah2[mt], bl2[nt][0], bl2[nt][1]);
                }
        }

        // ---- exp + pack P hi/lo as A-fragments ----
        uint32_t pa[2][4][4], pl[2][4][4];
        #pragma unroll
        for (int mt = 0; mt < 2; mt++)
            #pragma unroll
            for (int ks2 = 0; ks2 < 4; ks2++)
                #pragma unroll
                for (int jj = 0; jj < 2; jj++) {
                    float* sv = s[mt][2 * ks2 + jj];
                    float e0 = __expf(sv[0] * 0.125f), e1 = __expf(sv[1] * 0.125f);
                    float e2 = __expf(sv[2] * 0.125f), e3 = __expf(sv[3] * 0.125f);
                    lp[mt][0] += e0 + e1;
                    lp[mt][1] += e2 + e3;
                    uint32_t h01 = packbf(e0, e1), h23 = packbf(e2, e3);
                    __nv_bfloat162 H01 = *(__nv_bfloat162*)&h01;
                    __nv_bfloat162 H23 = *(__nv_bfloat162*)&h23;
                    pa[mt][ks2][jj * 2]     = h01;
                    pa[mt][ks2][jj * 2 + 1] = h23;
                    pl[mt][ks2][jj * 2]     = packbf(e0 - __low2float(H01),
                                                     e1 - __high2float(H01));
                    pl[mt][ks2][jj * 2 + 1] = packbf(e2 - __low2float(H23),
                                                     e3 - __high2float(H23));
                }

        // ---- O += P V (3 terms); V frags via ldmatrix.trans on [key][d] ----
        #pragma unroll
        for (int ks2 = 0; ks2 < 4; ks2++) {
            const int key0 = wn * 64 + ks2 * 16;
            uint32_t bh2[8][2], bl2[8][2];
            #pragma unroll
            for (int D = 0; D < 4; D++) {
                uint32_t so = SWZ((key0 + v_row) * 128 + D * 32 + v_cb);
                uint32_t r0, r1, r2, r3;
                ldsm4t(r0, r1, r2, r3, vh_s + so);
                bh2[2*D][0] = r0; bh2[2*D][1] = r1;
                bh2[2*D+1][0] = r2; bh2[2*D+1][1] = r3;
                ldsm4t(r0, r1, r2, r3, vl_s + so);
                bl2[2*D][0] = r0; bl2[2*D][1] = r1;
                bl2[2*D+1][0] = r2; bl2[2*D+1][1] = r3;
            }
            #pragma unroll
            for (int mt = 0; mt < 2; mt++)
                #pragma unroll
                for (int dt = 0; dt < 8; dt++) {
                    mma16816(o[mt][dt], pa[mt][ks2], bh2[dt][0], bh2[dt][1]);
                    mma16816(o[mt][dt], pl[mt][ks2], bh2[dt][0], bh2[dt][1]);
                    mma16816(o[mt][dt], pa[mt][ks2], bl2[dt][0], bl2[dt][1]);
                }
        }
        __syncthreads();
    }

    // ---- l reduce ----
    float* lbuf = (float*)(sm + ALBUF);
    #pragma unroll
    for (int mt = 0; mt < 2; mt++)
        #pragma unroll
        for (int rr = 0; rr < 2; rr++) {
            float v = lp[mt][rr];
            v += __shfl_xor_sync(0xFFFFFFFF, v, 1);
            v += __shfl_xor_sync(0xFFFFFFFF, v, 2);
            if ((lane & 3) == 0)
                lbuf[wn * 128 + wm * 32 + mt * 16 + rr * 8 + (lane >> 2)] = v;
        }
    __syncthreads();

    // ---- O reduce across wn via smem (reuse Q region) ----
    float* obuf = (float*)sm;
    if (wn == 1) {
        #pragma unroll
        for (int mt = 0; mt < 2; mt++) {
            int r0 = wm * 32 + mt * 16 + (lane >> 2);
            #pragma unroll
            for (int dt = 0; dt < 8; dt++) {
                int col = dt * 8 + (lane & 3) * 2;
                *(float2*)(obuf + r0 * 64 + col) = make_float2(o[mt][dt][0], o[mt][dt][1]);
                *(float2*)(obuf + (r0 + 8) * 64 + col) = make_float2(o[mt][dt][2], o[mt][dt][3]);
            }
        }
    }
    __syncthreads();
    if (wn == 0) {
        #pragma unroll
        for (int mt = 0; mt < 2; mt++) {
            int r0 = wm * 32 + mt * 16 + (lane >> 2);
            int r1 = r0 + 8;
            float inv0 = 1.0f / (lbuf[r0] + lbuf[128 + r0]);
            float inv1 = 1.0f / (lbuf[r1] + lbuf[128 + r1]);
            #pragma unroll
            for (int dt = 0; dt < 8; dt++) {
                int col = dt * 8 + (lane & 3) * 2;
                float2 p0 = *(float2*)(obuf + r0 * 64 + col);
                float2 p1 = *(float2*)(obuf + r1 * 64 + col);
                float v0 = (o[mt][dt][0] + p0.x) * inv0;
                float v1 = (o[mt][dt][1] + p0.y) * inv0;
                float v2 = (o[mt][dt][2] + p1.x) * inv1;
                float v3 = (o[mt][dt][3] + p1.y) * inv1;
                uint32_t h01 = packbf(v0, v1), h23 = packbf(v2, v3);
                __nv_bfloat162 H01 = *(__nv_bfloat162*)&h01, H23 = *(__nv_bfloat162*)&h23;
                uint32_t l01 = packbf(v0 - __low2float(H01), v1 - __high2float(H01));
                uint32_t l23 = packbf(v2 - __low2float(H23), v3 - __high2float(H23));
                size_t g0 = (size_t)(b * 4096 + qt * 128 + r0) * INNER + h * 64 + col;
                size_t g1 = (size_t)(b * 4096 + qt * 128 + r1) * INNER + h * 64 + col;
                *(uint32_t*)(aoh + g0) = h01;
                *(uint32_t*)(aoh + g1) = h23;
                *(uint32_t*)(aol + g0) = l01;
                *(uint32_t*)(aol + g1) = l23;
            }
        }
    }
}

// ---------------------------------------------------------------------------
extern "C" void kernel_launch(void* const* d_in, const int* in_sizes, int n_in,
                              void* d_out, int out_size)
{
    const float* x   = (const float*)d_in[0];
    const float* ctx = (const float*)d_in[1];
    const float* Wq  = (const float*)d_in[2];
    const float* Wkv = (const float*)d_in[3];
    const float* Wo  = (const float*)d_in[4];
    const float* bo  = (const float*)d_in[5];
    float* out = (float*)d_out;

    bf16 *xh, *xl, *ch, *cl, *wqh, *wql, *wkh, *wkl, *woh, *wol;
    bf16 *qh2, *ql2, *kvh, *kvl, *aoh, *aol;
    cudaGetSymbolAddress((void**)&xh,  g_xh);  cudaGetSymbolAddress((void**)&xl,  g_xl);
    cudaGetSymbolAddress((void**)&ch,  g_ch);  cudaGetSymbolAddress((void**)&cl,  g_cl);
    cudaGetSymbolAddress((void**)&wqh, g_wqh); cudaGetSymbolAddress((void**)&wql, g_wql);
    cudaGetSymbolAddress((void**)&wkh, g_wkh); cudaGetSymbolAddress((void**)&wkl, g_wkl);
    cudaGetSymbolAddress((void**)&woh, g_woh); cudaGetSymbolAddress((void**)&wol, g_wol);
    cudaGetSymbolAddress((void**)&qh2, g_qh);  cudaGetSymbolAddress((void**)&ql2, g_ql);
    cudaGetSymbolAddress((void**)&kvh, g_kvh); cudaGetSymbolAddress((void**)&kvl, g_kvl);
    cudaGetSymbolAddress((void**)&aoh, g_aoh); cudaGetSymbolAddress((void**)&aol, g_aol);

    cudaFuncSetAttribute(mm_gemm<0>, cudaFuncAttributeMaxDynamicSharedMemorySize, G_SM_TOTAL);
    cudaFuncSetAttribute(mm_gemm<1>, cudaFuncAttributeMaxDynamicSharedMemorySize, G_SM_TOTAL);
    cudaFuncSetAttribute(mm_attn,    cudaFuncAttributeMaxDynamicSharedMemorySize, A_SM_TOTAL);

    int n1 = NROWS * QDIM / 4, n2 = CROWS * QDIM / 4;
    split_plain4<<<(n1 + 255) / 256, 256>>>((const float4*)x, (uint2*)xh, (uint2*)xl, n1);
    split_plain4<<<(n2 + 255) / 256, 256>>>((const float4*)ctx, (uint2*)ch, (uint2*)cl, n2);
    split_transpose_t<<<dim3(INNER / 32, QDIM / 64), 256>>>(Wq,  wqh, wql, QDIM, INNER);
    split_transpose_t<<<dim3(KVDIM / 32, QDIM / 64), 256>>>(Wkv, wkh, wkl, QDIM, KVDIM);
    split_transpose_t<<<dim3(INNER / 32, INNER / 64), 256>>>(Wo, woh, wol, INNER, INNER);

    mm_gemm<0><<<dim3(INNER / 128, NROWS / 128), 256, G_SM_TOTAL>>>(
        xh, xl, wqh, wql, qh2, ql2, nullptr, nullptr, NROWS, INNER, QDIM);
    mm_gemm<0><<<dim3(KVDIM / 128, CROWS / 128), 256, G_SM_TOTAL>>>(
        ch, cl, wkh, wkl, kvh, kvl, nullptr, nullptr, CROWS, KVDIM, QDIM);

    mm_attn<<<512, 256, A_SM_TOTAL>>>(qh2, ql2, kvh, kvl, aoh, aol);

    mm_gemm<1><<<dim3(INNER / 128, NROWS / 128), 256, G_SM_TOTAL>>>(
        aoh, aol, woh, wol, nullptr, nullptr, out, bo, NROWS, INNER, INNER);
}